// round 5
// baseline (speedup 1.0000x reference)
#include <cuda_runtime.h>

// AdaptiveFilter: per-pixel learned bilateral filter, vertical blocking PY=4.
// out_c(p) = sum_k x_c(p+dk) * e_k / sum_k e_k,
//   e_k = 2^( w_k*log2e - (S*d_k)^2 ),  S = sqrt(50*log2e),
//   d_k = sum_c |g_c(p+dk)-g_c(p)|   (guidance pre-scaled by S in smem, so the
// exp argument is a single FFMA(d,-d,wl)).  Softmax normalizer cancels.
// Four vertically adjacent pixels per thread share 10x7 window rows.

namespace {
constexpr int B = 2, C = 3, H = 512, W = 512;
constexpr int BX = 32, BY = 4;       // 128 threads
constexpr int PY = 4;                // pixels per thread (vertical)
constexpr int TW = BX;               // 32
constexpr int TH = BY * PY;          // 16
constexpr int HALO = 3;
constexpr int SW = TW + 2 * HALO;    // 38
constexpr int SH = TH + 2 * HALO;    // 22
constexpr float LOG2E = 1.4426950408889634f;
constexpr float GS = 8.49321796f;    // sqrt(50*log2e)
}

__device__ __forceinline__ float ex2f(float v) {
    float r;
    asm("ex2.approx.f32 %0, %1;" : "=f"(r) : "f"(v));
    return r;
}

__global__ __launch_bounds__(BX * BY, 6)
void adaptive_filter_kernel(const float* __restrict__ x,
                            const float* __restrict__ g,
                            const float* __restrict__ w0,
                            float* __restrict__ out) {
    // Packed shared tiles: sgx = (S*g0, S*g1, S*g2, x0), sx2 = (x1, x2).
    __shared__ float4 sgx[SH][SW + 1];
    __shared__ float2 sx2[SH][SW + 1];

    const int b   = blockIdx.z;
    const int h0  = blockIdx.y * TH;
    const int w0c = blockIdx.x * TW;
    const int tid = threadIdx.y * BX + threadIdx.x;

    const float* __restrict__ gb = g + (size_t)b * C * H * W;
    const float* __restrict__ xb = x + (size_t)b * C * H * W;

    // Cooperative halo load with reflect padding (pad=3 << 512, one reflection).
    for (int idx = tid; idx < SH * SW; idx += BX * BY) {
        const int ty = idx / SW;
        const int tx = idx - ty * SW;
        int gy = h0 + ty - HALO;
        gy = gy < 0 ? -gy : (gy >= H ? 2 * H - 2 - gy : gy);
        int gx = w0c + tx - HALO;
        gx = gx < 0 ? -gx : (gx >= W ? 2 * W - 2 - gx : gx);
        const int p = gy * W + gx;
        sgx[ty][tx] = make_float4(gb[p] * GS, gb[H * W + p] * GS,
                                  gb[2 * H * W + p] * GS, xb[p]);
        sx2[ty][tx] = make_float2(xb[H * W + p], xb[2 * H * W + p]);
    }
    __syncthreads();

    const int tx  = threadIdx.x;
    const int py0 = threadIdx.y * PY;       // tile-local row of pixel 0
    const int h   = h0 + py0;
    const int w   = w0c + tx;

    // Per-pixel half-kernel logits: 16 contiguous floats = 4 float4 rows,
    // reloaded per window-row (rows repeat 0,1,2,3,2,1,0 -> L1 hits).
    const float4* __restrict__ wb0 =
        reinterpret_cast<const float4*>(w0) + ((size_t)b * H * W + (size_t)h * W + w) * 4;

    // Center guidance (pre-scaled) per pixel.
    float cx[PY], cy[PY], cz[PY];
#pragma unroll
    for (int p = 0; p < PY; ++p) {
        const float4 c = sgx[py0 + p + HALO][tx + HALO];
        cx[p] = c.x; cy[p] = c.y; cz[p] = c.z;
    }

    float n0[PY], n1[PY], n2[PY], den[PY];
#pragma unroll
    for (int p = 0; p < PY; ++p) { n0[p] = n1[p] = n2[p] = den[p] = 0.f; }

#pragma unroll
    for (int i = 0; i < PY + 6; ++i) {       // window rows py0+i
        const int row = py0 + i;

        // Kernel-row logits (pre-scaled by log2 e). Pixel p valid if 0<=i-p<=6.
        float wl[PY][4];
#pragma unroll
        for (int p = 0; p < PY; ++p) {
            if (i - p >= 0 && i - p <= 6) {
                const int kr = i - p;
                const int hi = kr < 4 ? kr : 6 - kr;
                const float4 t = __ldg(wb0 + (size_t)p * W * 4 + hi);
                wl[p][0] = t.x * LOG2E; wl[p][1] = t.y * LOG2E;
                wl[p][2] = t.z * LOG2E; wl[p][3] = t.w * LOG2E;
            }
        }

#pragma unroll
        for (int j = 0; j < 7; ++j) {
            const int hj = j < 4 ? j : 6 - j;
            // One shared read per (i,j) cell, consumed by all valid pixels.
            const float4 v = sgx[row][tx + j];
            const float2 u = sx2[row][tx + j];
#pragma unroll
            for (int p = 0; p < PY; ++p) {
                if (i - p < 0 || i - p > 6) continue;
                const float d = fabsf(v.x - cx[p]) + fabsf(v.y - cy[p]) +
                                fabsf(v.z - cz[p]);
                const float e = ex2f(fmaf(d, -d, wl[p][hj]));
                n0[p] = fmaf(v.w, e, n0[p]);
                n1[p] = fmaf(u.x, e, n1[p]);
                n2[p] = fmaf(u.y, e, n2[p]);
                den[p] += e;
            }
        }
    }

    const size_t o0 = ((size_t)b * C * H + (size_t)h) * W + w;
#pragma unroll
    for (int p = 0; p < PY; ++p) {
        const float inv = __fdividef(1.0f, den[p]);
        const size_t o = o0 + (size_t)p * W;
        out[o]                       = n0[p] * inv;
        out[o + (size_t)H * W]       = n1[p] * inv;
        out[o + (size_t)2 * H * W]   = n2[p] * inv;
    }
}

extern "C" void kernel_launch(void* const* d_in, const int* in_sizes, int n_in,
                              void* d_out, int out_size) {
    const float* x  = (const float*)d_in[0];
    const float* g  = (const float*)d_in[1];
    const float* w0 = (const float*)d_in[2];
    float* out = (float*)d_out;

    dim3 block(BX, BY);
    dim3 grid(W / TW, H / TH, B);
    adaptive_filter_kernel<<<grid, block>>>(x, g, w0, out);
}